// round 15
// baseline (speedup 1.0000x reference)
#include <cuda_runtime.h>
#include <math.h>

typedef unsigned long long ull;

// ---------------------------------------------------------------------------
// Problem constants
// ---------------------------------------------------------------------------
#define HWP   12544           // 112*112
#define NTOT  (8*128*HWP)     // 12,845,056

// ---------------------------------------------------------------------------
// Scratch pool (device global; no allocation allowed)
// ---------------------------------------------------------------------------
constexpr long SZ_CAT = 8L * 384 * HWP;
constexpr long SZ_GI  = 112L * 896 * 384;
constexpr long OFF_CAT = 0;
constexpr long OFF_X   = OFF_CAT + SZ_CAT;
constexpr long OFF_XH  = OFF_X   + NTOT;
constexpr long OFF_XW  = OFF_XH  + NTOT;
constexpr long OFF_GIH = OFF_XW  + NTOT;
constexpr long OFF_GIW = OFF_GIH + SZ_GI;
constexpr long OFF_OH  = OFF_GIW + SZ_GI;
constexpr long OFF_OW  = OFF_OH  + NTOT;
constexpr long OFF_WTH = OFF_OW  + NTOT;
constexpr long OFF_WTW = OFF_WTH + 49152;
constexpr long OFF_CTX = OFF_WTW + 49152;
constexpr long OFF_WTS = OFF_CTX + 2048;
constexpr long POOL_SZ = OFF_WTS + 16;
constexpr long OFF_T2  = OFF_CAT;
constexpr long OFF_X2  = OFF_XH;
constexpr long OFF_MOE = OFF_GIH;

__device__ float g_pool[POOL_SZ];

// ---------------------------------------------------------------------------
// helpers
// ---------------------------------------------------------------------------
__device__ __forceinline__ ull fma2(ull a, ull b, ull c) {
    ull d;
    asm("fma.rn.f32x2 %0, %1, %2, %3;" : "=l"(d) : "l"(a), "l"(b), "l"(c));
    return d;
}
__device__ __forceinline__ ull bcast2(float a) {
    ull d;
    asm("mov.b64 %0, {%1, %2};" : "=l"(d) : "f"(a), "f"(a));
    return d;
}
__device__ __forceinline__ ull pack2(float a, float b) {
    ull d;
    asm("mov.b64 %0, {%1, %2};" : "=l"(d) : "f"(a), "f"(b));
    return d;
}
__device__ __forceinline__ float2 unpk2(ull v) {
    float lo, hi;
    asm("mov.b64 {%0, %1}, %2;" : "=f"(lo), "=f"(hi) : "l"(v));
    return make_float2(lo, hi);
}
__device__ __forceinline__ unsigned f2tf(float x) {
    unsigned u;
    asm("cvt.rna.tf32.f32 %0, %1;" : "=r"(u) : "f"(x));
    return u;
}
__device__ __forceinline__ void mma_tf32(float* d, const unsigned* a, const unsigned* b) {
    asm volatile(
        "mma.sync.aligned.m16n8k8.row.col.f32.tf32.tf32.f32 "
        "{%0,%1,%2,%3}, {%4,%5,%6,%7}, {%8,%9}, {%0,%1,%2,%3};"
        : "+f"(d[0]), "+f"(d[1]), "+f"(d[2]), "+f"(d[3])
        : "r"(a[0]), "r"(a[1]), "r"(a[2]), "r"(a[3]), "r"(b[0]), "r"(b[1]));
}
__device__ __forceinline__ float sigm(float x) { return 1.f / (1.f + __expf(-x)); }
__device__ __forceinline__ float tanh_f(float x) { return 2.f / (1.f + __expf(-2.f * x)) - 1.f; }

// ---------------------------------------------------------------------------
// Resize taps
// ---------------------------------------------------------------------------
__device__ __forceinline__ void down_taps(int i, int* j, float* w) {
    float sum = 0.f;
#pragma unroll
    for (int t = 0; t < 4; ++t) {
        int jj = 2 * i - 1 + t;
        float raw = (t == 0 || t == 3) ? 0.25f : 0.75f;
        bool ok = (jj >= 0) && (jj < 224);
        w[t] = ok ? raw : 0.f;
        j[t] = ok ? jj : 0;
        sum += w[t];
    }
    float inv = 1.f / sum;
#pragma unroll
    for (int t = 0; t < 4; ++t) w[t] *= inv;
}
__device__ __forceinline__ void up_taps(int i, int& j0, int& j1, float& w0, float& w1) {
    int k = i >> 1;
    if ((i & 1) == 0) { j0 = k - 1; w0 = 0.25f; j1 = k;     w1 = 0.75f; }
    else              { j0 = k;     w0 = 0.75f; j1 = k + 1; w1 = 0.25f; }
    if (j0 < 0)  { j0 = 0;  w0 = 0.f; }
    if (j1 > 55) { j1 = 55; w1 = 0.f; }
    float inv = 1.f / (w0 + w1);
    w0 *= inv; w1 *= inv;
}

// ---------------------------------------------------------------------------
// Kernel 1: resize + concat
// ---------------------------------------------------------------------------
__global__ void resize_concat_kernel(const float* __restrict__ l,
                                     const float* __restrict__ m,
                                     const float* __restrict__ s,
                                     float* __restrict__ cat) {
    long idx = (long)blockIdx.x * 256 + threadIdx.x;
    if (idx >= NTOT) return;
    int w = idx % 112;
    int h = (idx / 112) % 112;
    int c = (idx / HWP) % 128;
    int b = (int)(idx / ((long)128 * HWP));
    long catb = (long)b * 384 * HWP;
    int p = h * 112 + w;

    cat[catb + (long)(128 + c) * HWP + p] = m[idx];
    {
        int jh[4], jw[4]; float wh[4], ww[4];
        down_taps(h, jh, wh);
        down_taps(w, jw, ww);
        const float* lp = l + (long)(b * 128 + c) * 224 * 224;
        float acc = 0.f;
#pragma unroll
        for (int a = 0; a < 4; ++a) {
            float rowv = 0.f;
#pragma unroll
            for (int bb = 0; bb < 4; ++bb)
                rowv += ww[bb] * lp[jh[a] * 224 + jw[bb]];
            acc += wh[a] * rowv;
        }
        cat[catb + (long)c * HWP + p] = acc;
    }
    {
        int j0, j1, i0, i1; float u0, u1, v0, v1;
        up_taps(h, j0, j1, u0, u1);
        up_taps(w, i0, i1, v0, v1);
        const float* sp = s + (long)(b * 128 + c) * 56 * 56;
        float acc = u0 * (v0 * sp[j0 * 56 + i0] + v1 * sp[j0 * 56 + i1])
                  + u1 * (v0 * sp[j1 * 56 + i0] + v1 * sp[j1 * 56 + i1]);
        cat[catb + (long)(256 + c) * HWP + p] = acc;
    }
}

// ---------------------------------------------------------------------------
// Kernel 2: weight transpose
// ---------------------------------------------------------------------------
__global__ void transpose_wih_kernel(const float* __restrict__ w, float* __restrict__ wT) {
    int i = blockIdx.x * 256 + threadIdx.x;
    if (i >= 49152) return;
    int j = i >> 7, k = i & 127;
    wT[k * 384 + j] = w[i];
}

// ---------------------------------------------------------------------------
// Shared GEMM params
// ---------------------------------------------------------------------------
struct GemmP {
    const float *A, *B1, *B2, *sv, *bv, *R1, *R2, *wts;
    float* C;
    int K, lda, ldb, ldc;
    long bzB, bzC, bzR;
};

// ---------------------------------------------------------------------------
// Tensor-core GEMM (tf32 mma.sync) — block 128(M0)x64(N), BK=16,
// 256 threads = 8 warps (4M x 2N), warp tile 32x32. Double-buffered smem,
// ONE __syncthreads per k-tile, global prefetch in regs.
// ALOAD: 0 = A row-major ptr (lda), 1 = gather x as xh rows, 2 = xw rows
// BLOAD: 0 normal, 1 B1+B2, 2 im2col 3x3 pad1 (z=(e<<3)|batch), 3 w0*B1+w1*B2
// EPI:   0 relu(acc*sv[m]+bv[m]), 1 acc+bv[n],
//        2 sigmoid(acc+bv[m])*(R1+R2), 3 relu(acc*sv[m]+bv[m])+R1
// ---------------------------------------------------------------------------
template <int ALOAD, int BLOAD, int EPI>
__global__ __launch_bounds__(256) void gemm_tc(GemmP p) {
    __shared__ __align__(16) unsigned As[2][128][20];
    __shared__ __align__(16) unsigned Bs[2][16][72];

    int z = blockIdx.z;
    const float* A  = p.A;
    const float* sv = p.sv;
    const float* bv = p.bv;
    if (BLOAD == 2) {
        int e = z >> 3;
        z &= 7;
        A  += (long)e * 128 * p.lda;
        sv += e * 128;
        bv += e * 128;
    }
    const float* B1 = p.B1 + (long)z * p.bzB;
    const float* B2 = (BLOAD == 1 || BLOAD == 3) ? p.B2 + (long)z * p.bzB : nullptr;
    float* C = p.C + (long)(BLOAD == 2 ? blockIdx.z : z) * p.bzC;
    const float* R1 = (EPI == 2 || EPI == 3) ? p.R1 + (long)z * p.bzR : nullptr;
    const float* R2 = (EPI == 2) ? p.R2 + (long)z * p.bzR : nullptr;
    float w0 = 0.f, w1 = 0.f;
    if (BLOAD == 3) { w0 = p.wts[z * 2]; w1 = p.wts[z * 2 + 1]; }

    int m0 = blockIdx.y * 128;
    int n0 = blockIdx.x * 64;
    int tid = threadIdx.x;
    int wid = tid >> 5, lane = tid & 31;
    int quad = lane >> 2, tig0 = lane & 3;
    int mw = (wid & 3) * 32, nw = (wid >> 2) * 32;

    int a_r = tid >> 1, a_k = (tid & 1) * 8;
    const float* Ap = nullptr;
    long aoff = 0;
    if (ALOAD == 0) {
        Ap = A + (long)(m0 + a_r) * p.lda + a_k;
    } else {
        int r = m0 + a_r;
        int t = r / 896;
        int rem = r - t * 896;
        int b = rem / 112;
        int q = rem - b * 112;
        aoff = (long)b * 128 * HWP + (ALOAD == 1 ? (t * 112 + q) : (q * 112 + t));
    }

    int b_r = 0, b_c = 0;
    int s_k[4], s_n[4], s_nh[4], s_nw[4];
    if (BLOAD == 2) {
#pragma unroll
        for (int i = 0; i < 4; ++i) {
            int idx = tid + i * 256;
            s_k[i] = idx >> 6;
            int nl = idx & 63;
            s_n[i] = nl;
            int n = n0 + nl;
            s_nh[i] = n / 112;
            s_nw[i] = n % 112;
        }
    } else {
        b_r = tid >> 4;
        b_c = (tid & 15) * 4;
    }

    float aF[8];
    float4 bR;
    float  bS[4];

    auto loadTile = [&](int k0) {
        if (ALOAD == 0) {
            float4 v0 = *(const float4*)(Ap + k0);
            float4 v1 = *(const float4*)(Ap + k0 + 4);
            aF[0] = v0.x; aF[1] = v0.y; aF[2] = v0.z; aF[3] = v0.w;
            aF[4] = v1.x; aF[5] = v1.y; aF[6] = v1.z; aF[7] = v1.w;
        } else {
#pragma unroll
            for (int j = 0; j < 8; ++j)
                aF[j] = A[aoff + (long)(k0 + a_k + j) * HWP];
        }
        if (BLOAD == 2) {
#pragma unroll
            for (int i = 0; i < 4; ++i) {
                int kk = k0 + s_k[i];
                int cch = kk / 9, q = kk - cch * 9;
                int dy = q / 3, dx = q - dy * 3;
                int h = s_nh[i] + dy - 1;
                int w = s_nw[i] + dx - 1;
                bS[i] = (h >= 0 && h < 112 && w >= 0 && w < 112)
                            ? B1[((long)cch * 112 + h) * 112 + w] : 0.f;
            }
        } else {
            long off = (long)(k0 + b_r) * p.ldb + n0 + b_c;
            float4 v = *(const float4*)(B1 + off);
            if (BLOAD == 1) {
                float4 u = *(const float4*)(B2 + off);
                v.x += u.x; v.y += u.y; v.z += u.z; v.w += u.w;
            } else if (BLOAD == 3) {
                float4 u = *(const float4*)(B2 + off);
                v.x = w0 * v.x + w1 * u.x; v.y = w0 * v.y + w1 * u.y;
                v.z = w0 * v.z + w1 * u.z; v.w = w0 * v.w + w1 * u.w;
            }
            bR = v;
        }
    };
    auto storeTile = [&](int buf) {
        uint4 t0 = make_uint4(f2tf(aF[0]), f2tf(aF[1]), f2tf(aF[2]), f2tf(aF[3]));
        uint4 t1 = make_uint4(f2tf(aF[4]), f2tf(aF[5]), f2tf(aF[6]), f2tf(aF[7]));
        *(uint4*)&As[buf][a_r][a_k]     = t0;
        *(uint4*)&As[buf][a_r][a_k + 4] = t1;
        if (BLOAD == 2) {
#pragma unroll
            for (int i = 0; i < 4; ++i) Bs[buf][s_k[i]][s_n[i]] = f2tf(bS[i]);
        } else {
            uint4 t = make_uint4(f2tf(bR.x), f2tf(bR.y), f2tf(bR.z), f2tf(bR.w));
            *(uint4*)&Bs[buf][b_r][b_c] = t;
        }
    };

    float acc[2][4][4];
#pragma unroll
    for (int a = 0; a < 2; ++a)
#pragma unroll
        for (int b = 0; b < 4; ++b)
#pragma unroll
            for (int c = 0; c < 4; ++c) acc[a][b][c] = 0.f;

    loadTile(0);
    storeTile(0);
    __syncthreads();
    int buf = 0;
    for (int k0 = 0; k0 < p.K; k0 += 16) {
        bool more = (k0 + 16 < p.K);
        if (more) loadTile(k0 + 16);
#pragma unroll
        for (int k8 = 0; k8 < 2; ++k8) {
            int kb = k8 * 8;
            unsigned af[2][4], bf[4][2];
#pragma unroll
            for (int mf = 0; mf < 2; ++mf) {
                int r = mw + mf * 16 + quad;
                af[mf][0] = As[buf][r][kb + tig0];
                af[mf][1] = As[buf][r + 8][kb + tig0];
                af[mf][2] = As[buf][r][kb + tig0 + 4];
                af[mf][3] = As[buf][r + 8][kb + tig0 + 4];
            }
#pragma unroll
            for (int nf = 0; nf < 4; ++nf) {
                int cb = nw + nf * 8 + quad;
                bf[nf][0] = Bs[buf][kb + tig0][cb];
                bf[nf][1] = Bs[buf][kb + tig0 + 4][cb];
            }
#pragma unroll
            for (int mf = 0; mf < 2; ++mf)
#pragma unroll
                for (int nf = 0; nf < 4; ++nf)
                    mma_tf32(acc[mf][nf], af[mf], bf[nf]);
        }
        if (more) storeTile(buf ^ 1);
        __syncthreads();
        buf ^= 1;
    }

    // epilogue
#pragma unroll
    for (int mf = 0; mf < 2; ++mf) {
#pragma unroll
        for (int half = 0; half < 2; ++half) {
            int m = mw + mf * 16 + quad + half * 8;
            float sc = 0.f, bb = 0.f;
            if (EPI == 0 || EPI == 3) { sc = sv[m]; bb = bv[m]; }
            if (EPI == 2) { bb = bv[m]; }
#pragma unroll
            for (int nf = 0; nf < 4; ++nf) {
                int n = n0 + nw + nf * 8 + tig0 * 2;
                long o = (long)(m0 + m) * p.ldc + n;
                float vx = acc[mf][nf][half * 2 + 0];
                float vy = acc[mf][nf][half * 2 + 1];
                if (EPI == 0) {
                    vx = fmaxf(vx * sc + bb, 0.f);
                    vy = fmaxf(vy * sc + bb, 0.f);
                } else if (EPI == 1) {
                    float2 bn = *(const float2*)(bv + n);
                    vx += bn.x; vy += bn.y;
                } else if (EPI == 2) {
                    float2 r1 = *(const float2*)(R1 + o);
                    float2 r2 = *(const float2*)(R2 + o);
                    vx = sigm(vx + bb) * (r1.x + r2.x);
                    vy = sigm(vy + bb) * (r1.y + r2.y);
                } else {
                    float2 r1 = *(const float2*)(R1 + o);
                    vx = fmaxf(vx * sc + bb, 0.f) + r1.x;
                    vy = fmaxf(vy * sc + bb, 0.f) + r1.y;
                }
                *(float2*)(C + o) = make_float2(vx, vy);
            }
        }
    }
}

// ---------------------------------------------------------------------------
// Kernel 3: persistent GRU scan — f32x2 over sequence pairs.
// 128 blocks: 0..63 h-scan, 64..127 w-scan. Each block: 14 seqs = 7 pairs
// of one batch slice. 256 threads = 2 subs x 128 channels; sub0: pairs 0-3,
// sub1: pairs 4-6 (imbalance off critical path). Whh at pad-129 scalar
// (conflict-free); h-state as broadcast ull Hs2[k][8]. Per-sub named bars.
// ---------------------------------------------------------------------------
__global__ __launch_bounds__(256) void scan_kernel(
    const float* __restrict__ whh_h, const float* __restrict__ bhh_h,
    const float* __restrict__ whh_w, const float* __restrict__ bhh_w,
    const float* __restrict__ gih, const float* __restrict__ giw,
    float* __restrict__ oh, float* __restrict__ ow)
{
    extern __shared__ float sm[];
    float* Ws = sm;                       // 384 * 129 floats
    ull* Hs2  = (ull*)(sm + 384 * 129);   // [128][8] pairs (slots 0..6 used)

    int dir = blockIdx.x >> 6;
    int blk = blockIdx.x & 63;
    const float* W   = dir ? whh_w : whh_h;
    const float* bhh = dir ? bhh_w : bhh_h;
    const float* gi  = dir ? giw : gih;
    float* outp      = dir ? ow : oh;

    for (int i = threadIdx.x; i < 384 * 128; i += 256)
        Ws[(i >> 7) * 129 + (i & 127)] = W[i];
    for (int i = threadIdx.x; i < 128 * 8; i += 256) Hs2[i] = 0ull;

    int c   = threadIdx.x & 127;
    int sub = threadIdx.x >> 7;
    int npair = 4 - sub;           // sub0: 4 pairs, sub1: 3 pairs
    int pbase = sub * 4;

    float br = bhh[c], bz = bhh[128 + c], bn = bhh[256 + c];
    ull br2 = bcast2(br), bz2 = bcast2(bz), bn2 = bcast2(bn);

    int b    = blk >> 3;           // batch (8 blocks per batch)
    int posb = (blk & 7) * 14;     // position base within batch

    long gb[4], ob[4];
#pragma unroll
    for (int p = 0; p < 4; ++p) {
        int pp = pbase + p;
        int pos = posb + 2 * pp;
        gb[p] = ((long)(b * 112 + pos)) * 384 + c;
        long base = (long)(b * 128 + c) * 12544;
        ob[p] = dir ? (base + (long)pos * 112) : (base + pos);
    }
    int ostep = dir ? 1 : 112;     // step along t

    const float* wr_p = Ws + c * 129;
    const float* wz_p = Ws + (128 + c) * 129;
    const float* wn_p = Ws + (256 + c) * 129;
    __syncthreads();

    for (int t = 0; t < 112; ++t) {
        const float* gip = gi + (long)t * 344064;  // 896*384
        float gr[8], gz[8], gn[8];
#pragma unroll
        for (int p = 0; p < 4; ++p) if (p < npair) {
            long g = gb[p];
            gr[2*p]   = gip[g];       gz[2*p]   = gip[g + 128]; gn[2*p]   = gip[g + 256];
            gr[2*p+1] = gip[g + 384]; gz[2*p+1] = gip[g + 512]; gn[2*p+1] = gip[g + 640];
        }
        ull aR[4], aZ[4], aN[4];
#pragma unroll
        for (int p = 0; p < 4; ++p) { aR[p] = br2; aZ[p] = bz2; aN[p] = bn2; }

#pragma unroll 4
        for (int k = 0; k < 128; ++k) {
            ull wr2 = bcast2(wr_p[k]);
            ull wz2 = bcast2(wz_p[k]);
            ull wn2 = bcast2(wn_p[k]);
            const ull* hp = &Hs2[k * 8 + pbase];
#pragma unroll
            for (int p = 0; p < 4; ++p) if (p < npair) {
                ull h2 = hp[p];
                aR[p] = fma2(wr2, h2, aR[p]);
                aZ[p] = fma2(wz2, h2, aZ[p]);
                aN[p] = fma2(wn2, h2, aN[p]);
            }
        }

        float hn[8];
#pragma unroll
        for (int p = 0; p < 4; ++p) if (p < npair) {
            float2 ar = unpk2(aR[p]), az = unpk2(aZ[p]), an = unpk2(aN[p]);
            float2 hold = unpk2(Hs2[c * 8 + pbase + p]);
            float r0 = sigm(gr[2*p]   + ar.x);
            float z0 = sigm(gz[2*p]   + az.x);
            float n0 = tanh_f(gn[2*p]   + r0 * an.x);
            hn[2*p]   = (1.f - z0) * n0 + z0 * hold.x;
            float r1 = sigm(gr[2*p+1] + ar.y);
            float z1 = sigm(gz[2*p+1] + az.y);
            float n1 = tanh_f(gn[2*p+1] + r1 * an.y);
            hn[2*p+1] = (1.f - z1) * n1 + z1 * hold.y;
        }
        asm volatile("bar.sync %0, 128;" :: "r"(sub + 1) : "memory");
#pragma unroll
        for (int p = 0; p < 4; ++p) if (p < npair) {
            Hs2[c * 8 + pbase + p] = pack2(hn[2*p], hn[2*p+1]);
            long o = ob[p] + (long)t * ostep;
            if (dir == 0) {
                *(float2*)(outp + o) = make_float2(hn[2*p], hn[2*p+1]);
            } else {
                outp[o]       = hn[2*p];
                outp[o + 112] = hn[2*p+1];
            }
        }
        asm volatile("bar.sync %0, 128;" :: "r"(sub + 1) : "memory");
    }
}

// ---------------------------------------------------------------------------
// Router
// ---------------------------------------------------------------------------
__global__ void router_stats_kernel(const float* __restrict__ x2, float* __restrict__ ctx) {
    int b = blockIdx.x >> 7;
    int c = blockIdx.x & 127;
    const float* p = x2 + (long)(b * 128 + c) * HWP;
    float gs = 0.f, fs = 0.f;
    for (int i = threadIdx.x; i < HWP; i += 256) {
        int h = i / 112, w = i - h * 112;
        float v = p[i];
        gs += v;
        float lap = 4.f * v;
        if (h > 0)   lap -= p[i - 112];
        if (h < 111) lap -= p[i + 112];
        if (w > 0)   lap -= p[i - 1];
        if (w < 111) lap -= p[i + 1];
        fs += fabsf(lap);
    }
    __shared__ float sg[256], sf[256];
    sg[threadIdx.x] = gs; sf[threadIdx.x] = fs;
    __syncthreads();
    for (int st = 128; st > 0; st >>= 1) {
        if (threadIdx.x < st) {
            sg[threadIdx.x] += sg[threadIdx.x + st];
            sf[threadIdx.x] += sf[threadIdx.x + st];
        }
        __syncthreads();
    }
    if (threadIdx.x == 0) {
        ctx[b * 256 + c]       = sg[0] * (1.f / 12544.f);
        ctx[b * 256 + 128 + c] = sf[0] * (1.f / 12544.f);
    }
}

__global__ void router_fc_kernel(const float* __restrict__ ctx,
                                 const float* __restrict__ fcw,
                                 const float* __restrict__ fcb,
                                 float* __restrict__ wts) {
    int b = threadIdx.x >> 5;
    int lane = threadIdx.x & 31;
    float l0 = 0.f, l1 = 0.f;
    for (int j = lane; j < 256; j += 32) {
        float v = ctx[b * 256 + j];
        l0 += v * fcw[j];
        l1 += v * fcw[256 + j];
    }
#pragma unroll
    for (int off = 16; off; off >>= 1) {
        l0 += __shfl_down_sync(0xffffffffu, l0, off);
        l1 += __shfl_down_sync(0xffffffffu, l1, off);
    }
    if (lane == 0) {
        l0 += fcb[0]; l1 += fcb[1];
        float mx = fmaxf(l0, l1);
        float e0 = expf(l0 - mx), e1 = expf(l1 - mx);
        float inv = 1.f / (e0 + e1);
        wts[b * 2]     = e0 * inv;
        wts[b * 2 + 1] = e1 * inv;
    }
}

// ---------------------------------------------------------------------------
// Launch
// ---------------------------------------------------------------------------
extern "C" void kernel_launch(void* const* d_in, const int* in_sizes, int n_in,
                              void* d_out, int out_size) {
    const float* l        = (const float*)d_in[0];
    const float* m        = (const float*)d_in[1];
    const float* s        = (const float*)d_in[2];
    const float* p_in_w   = (const float*)d_in[3];
    const float* p_in_s   = (const float*)d_in[4];
    const float* p_in_b   = (const float*)d_in[5];
    const float* gh_wih   = (const float*)d_in[6];
    const float* gh_whh   = (const float*)d_in[7];
    const float* gh_bih   = (const float*)d_in[8];
    const float* gh_bhh   = (const float*)d_in[9];
    const float* gw_wih   = (const float*)d_in[10];
    const float* gw_whh   = (const float*)d_in[11];
    const float* gw_bih   = (const float*)d_in[12];
    const float* gw_bhh   = (const float*)d_in[13];
    const float* gate_w   = (const float*)d_in[14];
    const float* gate_b   = (const float*)d_in[15];
    const float* p_out_w  = (const float*)d_in[16];
    const float* p_out_s  = (const float*)d_in[17];
    const float* p_out_b  = (const float*)d_in[18];
    const float* exp_w    = (const float*)d_in[19];
    const float* exp_s    = (const float*)d_in[20];
    const float* exp_b    = (const float*)d_in[21];
    const float* fc_w     = (const float*)d_in[22];
    const float* fc_b     = (const float*)d_in[23];
    const float* fuse_w   = (const float*)d_in[24];
    const float* fuse_s   = (const float*)d_in[25];
    const float* fuse_b   = (const float*)d_in[26];

    float* pool = nullptr;
    cudaGetSymbolAddress((void**)&pool, g_pool);

    const int SCAN_SMEM = 384 * 129 * 4 + 128 * 8 * 8;  // 206,336 B
    cudaFuncSetAttribute(scan_kernel, cudaFuncAttributeMaxDynamicSharedMemorySize, SCAN_SMEM);

    const int NBLK = (NTOT + 255) / 256;
    const dim3 TC_GRID(196, 1, 8);

    // 1. resize + concat, weight transposes
    resize_concat_kernel<<<NBLK, 256>>>(l, m, s, pool + OFF_CAT);
    transpose_wih_kernel<<<192, 256>>>(gh_wih, pool + OFF_WTH);
    transpose_wih_kernel<<<192, 256>>>(gw_wih, pool + OFF_WTW);

    // 2. p_in (tf32 TC)
    {
        GemmP P = {};
        P.A = p_in_w; P.lda = 384; P.K = 384;
        P.B1 = pool + OFF_CAT; P.ldb = HWP; P.bzB = 384L * HWP;
        P.C = pool + OFF_X; P.ldc = HWP; P.bzC = 128L * HWP;
        P.sv = p_in_s; P.bv = p_in_b;
        gemm_tc<0, 0, 0><<<TC_GRID, 256>>>(P);
    }

    // 3. gi GEMMs (tf32 TC, pack fused into A-gather)
    {
        GemmP P = {};
        P.A = pool + OFF_X; P.K = 128;
        P.B1 = pool + OFF_WTH; P.ldb = 384; P.bzB = 0;
        P.C = pool + OFF_GIH; P.ldc = 384; P.bzC = 0;
        P.bv = gh_bih;
        gemm_tc<1, 0, 1><<<dim3(6, 784, 1), 256>>>(P);
        P.B1 = pool + OFF_WTW;
        P.C = pool + OFF_GIW; P.bv = gw_bih;
        gemm_tc<2, 0, 1><<<dim3(6, 784, 1), 256>>>(P);
    }

    // 4. GRU scans (f32x2 pairs)
    scan_kernel<<<128, 256, SCAN_SMEM>>>(gh_whh, gh_bhh, gw_whh, gw_bhh,
                                         pool + OFF_GIH, pool + OFF_GIW,
                                         pool + OFF_OH, pool + OFF_OW);

    // 5. gate (tf32 TC)
    {
        GemmP P = {};
        P.A = gate_w; P.lda = 128; P.K = 128;
        P.B1 = pool + OFF_OH; P.B2 = pool + OFF_OW; P.ldb = HWP; P.bzB = 128L * HWP;
        P.C = pool + OFF_T2; P.ldc = HWP; P.bzC = 128L * HWP;
        P.bv = gate_b;
        P.R1 = pool + OFF_OH; P.R2 = pool + OFF_OW; P.bzR = 128L * HWP;
        gemm_tc<0, 1, 2><<<TC_GRID, 256>>>(P);
    }

    // 6. p_out (tf32 TC)
    {
        GemmP P = {};
        P.A = p_out_w; P.lda = 128; P.K = 128;
        P.B1 = pool + OFF_T2; P.ldb = HWP; P.bzB = 128L * HWP;
        P.C = pool + OFF_X2; P.ldc = HWP; P.bzC = 128L * HWP;
        P.sv = p_out_s; P.bv = p_out_b;
        P.R1 = pool + OFF_X; P.bzR = 128L * HWP;
        gemm_tc<0, 0, 3><<<TC_GRID, 256>>>(P);
    }

    // 7. router
    router_stats_kernel<<<1024, 256>>>(pool + OFF_X2, pool + OFF_CTX);
    router_fc_kernel<<<1, 256>>>(pool + OFF_CTX, fc_w, fc_b, pool + OFF_WTS);

    // 8. experts (tf32 TC, both experts in ONE launch: z = (e<<3)|batch)
    {
        GemmP P = {};
        P.A = exp_w; P.lda = 1152; P.K = 1152;
        P.B1 = pool + OFF_X2; P.bzB = 128L * HWP;
        P.C = pool + OFF_MOE; P.ldc = HWP; P.bzC = 128L * HWP;
        P.sv = exp_s; P.bv = exp_b;
        gemm_tc<0, 2, 0><<<dim3(196, 1, 16), 256>>>(P);
    }

    // 9. fuse (tf32 TC)
    {
        GemmP P = {};
        P.A = fuse_w; P.lda = 128; P.K = 128;
        P.B1 = pool + OFF_MOE; P.B2 = pool + OFF_MOE + NTOT;
        P.ldb = HWP; P.bzB = 128L * HWP;
        P.wts = pool + OFF_WTS;
        P.C = (float*)d_out; P.ldc = HWP; P.bzC = 128L * HWP;
        P.sv = fuse_s; P.bv = fuse_b;
        gemm_tc<0, 3, 0><<<TC_GRID, 256>>>(P);
    }
}

// round 16
// speedup vs baseline: 1.1383x; 1.1383x over previous
#include <cuda_runtime.h>
#include <math.h>

typedef unsigned long long ull;

// ---------------------------------------------------------------------------
// Problem constants
// ---------------------------------------------------------------------------
#define HWP   12544           // 112*112
#define NTOT  (8*128*HWP)     // 12,845,056

// ---------------------------------------------------------------------------
// Scratch pool (device global; no allocation allowed)
// ---------------------------------------------------------------------------
constexpr long SZ_CAT = 8L * 384 * HWP;
constexpr long SZ_GI  = 112L * 896 * 384;
constexpr long OFF_CAT = 0;
constexpr long OFF_X   = OFF_CAT + SZ_CAT;
constexpr long OFF_XH  = OFF_X   + NTOT;
constexpr long OFF_XW  = OFF_XH  + NTOT;
constexpr long OFF_GIH = OFF_XW  + NTOT;
constexpr long OFF_GIW = OFF_GIH + SZ_GI;
constexpr long OFF_OH  = OFF_GIW + SZ_GI;
constexpr long OFF_OW  = OFF_OH  + NTOT;
constexpr long OFF_WTH = OFF_OW  + NTOT;
constexpr long OFF_WTW = OFF_WTH + 49152;
constexpr long OFF_CTX = OFF_WTW + 49152;
constexpr long OFF_WTS = OFF_CTX + 2048;
constexpr long POOL_SZ = OFF_WTS + 16;
constexpr long OFF_T2  = OFF_CAT;
constexpr long OFF_X2  = OFF_XH;
constexpr long OFF_MOE = OFF_GIH;

__device__ float g_pool[POOL_SZ];

// ---------------------------------------------------------------------------
// helpers
// ---------------------------------------------------------------------------
__device__ __forceinline__ unsigned f2tf(float x) {
    unsigned u;
    asm("cvt.rna.tf32.f32 %0, %1;" : "=r"(u) : "f"(x));
    return u;
}
__device__ __forceinline__ void mma_tf32(float* d, const unsigned* a, const unsigned* b) {
    asm volatile(
        "mma.sync.aligned.m16n8k8.row.col.f32.tf32.tf32.f32 "
        "{%0,%1,%2,%3}, {%4,%5,%6,%7}, {%8,%9}, {%0,%1,%2,%3};"
        : "+f"(d[0]), "+f"(d[1]), "+f"(d[2]), "+f"(d[3])
        : "r"(a[0]), "r"(a[1]), "r"(a[2]), "r"(a[3]), "r"(b[0]), "r"(b[1]));
}
__device__ __forceinline__ float sigm(float x) { return 1.f / (1.f + __expf(-x)); }
__device__ __forceinline__ float tanh_f(float x) { return 2.f / (1.f + __expf(-2.f * x)) - 1.f; }

// ---------------------------------------------------------------------------
// Resize taps
// ---------------------------------------------------------------------------
__device__ __forceinline__ void down_taps(int i, int* j, float* w) {
    float sum = 0.f;
#pragma unroll
    for (int t = 0; t < 4; ++t) {
        int jj = 2 * i - 1 + t;
        float raw = (t == 0 || t == 3) ? 0.25f : 0.75f;
        bool ok = (jj >= 0) && (jj < 224);
        w[t] = ok ? raw : 0.f;
        j[t] = ok ? jj : 0;
        sum += w[t];
    }
    float inv = 1.f / sum;
#pragma unroll
    for (int t = 0; t < 4; ++t) w[t] *= inv;
}
__device__ __forceinline__ void up_taps(int i, int& j0, int& j1, float& w0, float& w1) {
    int k = i >> 1;
    if ((i & 1) == 0) { j0 = k - 1; w0 = 0.25f; j1 = k;     w1 = 0.75f; }
    else              { j0 = k;     w0 = 0.75f; j1 = k + 1; w1 = 0.25f; }
    if (j0 < 0)  { j0 = 0;  w0 = 0.f; }
    if (j1 > 55) { j1 = 55; w1 = 0.f; }
    float inv = 1.f / (w0 + w1);
    w0 *= inv; w1 *= inv;
}

// ---------------------------------------------------------------------------
// Kernel 1: resize + concat
// ---------------------------------------------------------------------------
__global__ void resize_concat_kernel(const float* __restrict__ l,
                                     const float* __restrict__ m,
                                     const float* __restrict__ s,
                                     float* __restrict__ cat) {
    long idx = (long)blockIdx.x * 256 + threadIdx.x;
    if (idx >= NTOT) return;
    int w = idx % 112;
    int h = (idx / 112) % 112;
    int c = (idx / HWP) % 128;
    int b = (int)(idx / ((long)128 * HWP));
    long catb = (long)b * 384 * HWP;
    int p = h * 112 + w;

    cat[catb + (long)(128 + c) * HWP + p] = m[idx];
    {
        int jh[4], jw[4]; float wh[4], ww[4];
        down_taps(h, jh, wh);
        down_taps(w, jw, ww);
        const float* lp = l + (long)(b * 128 + c) * 224 * 224;
        float acc = 0.f;
#pragma unroll
        for (int a = 0; a < 4; ++a) {
            float rowv = 0.f;
#pragma unroll
            for (int bb = 0; bb < 4; ++bb)
                rowv += ww[bb] * lp[jh[a] * 224 + jw[bb]];
            acc += wh[a] * rowv;
        }
        cat[catb + (long)c * HWP + p] = acc;
    }
    {
        int j0, j1, i0, i1; float u0, u1, v0, v1;
        up_taps(h, j0, j1, u0, u1);
        up_taps(w, i0, i1, v0, v1);
        const float* sp = s + (long)(b * 128 + c) * 56 * 56;
        float acc = u0 * (v0 * sp[j0 * 56 + i0] + v1 * sp[j0 * 56 + i1])
                  + u1 * (v0 * sp[j1 * 56 + i0] + v1 * sp[j1 * 56 + i1]);
        cat[catb + (long)(256 + c) * HWP + p] = acc;
    }
}

// ---------------------------------------------------------------------------
// Kernel 2: weight transpose
// ---------------------------------------------------------------------------
__global__ void transpose_wih_kernel(const float* __restrict__ w, float* __restrict__ wT) {
    int i = blockIdx.x * 256 + threadIdx.x;
    if (i >= 49152) return;
    int j = i >> 7, k = i & 127;
    wT[k * 384 + j] = w[i];
}

// ---------------------------------------------------------------------------
// Shared GEMM params
// ---------------------------------------------------------------------------
struct GemmP {
    const float *A, *B1, *B2, *sv, *bv, *R1, *R2, *wts;
    float* C;
    int K, lda, ldb, ldc;
    long bzB, bzC, bzR;
};

// ---------------------------------------------------------------------------
// Tensor-core GEMM v4 (tf32 mma.sync).
// Block 128(M) x 128(N), BK=16, 256 threads = 8 warps (2M x 4N),
// warp tile 64x32 (4 m16-frags x 4 n8-frags = 16 mma / k8).
// Fragment traffic 187B/mma (vs 256 for 32x32 tile); still 8 warps/block
// so occupancy holds (~105 regs -> 2 blocks/SM).
// As [m][k] pad 20, Bs [k][n] pad 136 (both conflict-free for frag loads).
// Double-buffered, ONE __syncthreads per k-tile, global prefetch in regs.
// ALOAD: 0 = A row-major ptr (lda), 1 = gather x as xh rows, 2 = xw rows
// BLOAD: 0 normal, 1 B1+B2, 2 im2col 3x3 pad1 (z=(e<<3)|batch), 3 w0*B1+w1*B2
// EPI:   0 relu(acc*sv[m]+bv[m]), 1 acc+bv[n],
//        2 sigmoid(acc+bv[m])*(R1+R2), 3 relu(acc*sv[m]+bv[m])+R1
// ---------------------------------------------------------------------------
template <int ALOAD, int BLOAD, int EPI>
__global__ __launch_bounds__(256) void gemm_tc(GemmP p) {
    __shared__ __align__(16) unsigned As[2][128][20];   // [m][k] pad 20
    __shared__ __align__(16) unsigned Bs[2][16][136];   // [k][n] pad 136

    int z = blockIdx.z;
    const float* A  = p.A;
    const float* sv = p.sv;
    const float* bv = p.bv;
    if (BLOAD == 2) {
        int e = z >> 3;
        z &= 7;
        A  += (long)e * 128 * p.lda;
        sv += e * 128;
        bv += e * 128;
    }
    const float* B1 = p.B1 + (long)z * p.bzB;
    const float* B2 = (BLOAD == 1 || BLOAD == 3) ? p.B2 + (long)z * p.bzB : nullptr;
    float* C = p.C + (long)(BLOAD == 2 ? blockIdx.z : z) * p.bzC;
    const float* R1 = (EPI == 2 || EPI == 3) ? p.R1 + (long)z * p.bzR : nullptr;
    const float* R2 = (EPI == 2) ? p.R2 + (long)z * p.bzR : nullptr;
    float w0 = 0.f, w1 = 0.f;
    if (BLOAD == 3) { w0 = p.wts[z * 2]; w1 = p.wts[z * 2 + 1]; }

    int m0 = blockIdx.y * 128;
    int n0 = blockIdx.x * 128;
    int tid = threadIdx.x;
    int wid = tid >> 5, lane = tid & 31;
    int quad = lane >> 2, tig = lane & 3;
    int mw = (wid & 1) * 64, nw = (wid >> 1) * 32;

    // A global slot: one row per pair of threads, 8 k each
    int a_r = tid >> 1, a_k = (tid & 1) * 8;
    const float* Ap = nullptr;
    long aoff = 0;
    if (ALOAD == 0) {
        Ap = A + (long)(m0 + a_r) * p.lda + a_k;
    } else {
        int r = m0 + a_r;
        int t = r / 896;
        int rem = r - t * 896;
        int b = rem / 112;
        int q = rem - b * 112;
        aoff = (long)b * 128 * HWP + (ALOAD == 1 ? (t * 112 + q) : (q * 112 + t));
    }

    // B slots: 16 k x 128 n = 2048 elems
    int b_r[2], b_c[2];
    int s_k[8], s_n[8], s_nh[8], s_nw[8];
    if (BLOAD == 2) {
#pragma unroll
        for (int i = 0; i < 8; ++i) {
            int idx = tid + i * 256;
            s_k[i] = idx >> 7;
            int nl = idx & 127;
            s_n[i] = nl;
            int n = n0 + nl;
            s_nh[i] = n / 112;
            s_nw[i] = n % 112;
        }
    } else {
#pragma unroll
        for (int i = 0; i < 2; ++i) {
            int idx = tid + i * 256;
            b_r[i] = idx >> 5;
            b_c[i] = (idx & 31) * 4;
        }
    }

    float aF[8];
    float4 bR[2];
    float  bS[8];

    auto loadTile = [&](int k0) {
        if (ALOAD == 0) {
            float4 v0 = *(const float4*)(Ap + k0);
            float4 v1 = *(const float4*)(Ap + k0 + 4);
            aF[0] = v0.x; aF[1] = v0.y; aF[2] = v0.z; aF[3] = v0.w;
            aF[4] = v1.x; aF[5] = v1.y; aF[6] = v1.z; aF[7] = v1.w;
        } else {
#pragma unroll
            for (int j = 0; j < 8; ++j)
                aF[j] = A[aoff + (long)(k0 + a_k + j) * HWP];
        }
        if (BLOAD == 2) {
#pragma unroll
            for (int i = 0; i < 8; ++i) {
                int kk = k0 + s_k[i];
                int cch = kk / 9, q = kk - cch * 9;
                int dy = q / 3, dx = q - dy * 3;
                int h = s_nh[i] + dy - 1;
                int w = s_nw[i] + dx - 1;
                bS[i] = (h >= 0 && h < 112 && w >= 0 && w < 112)
                            ? B1[((long)cch * 112 + h) * 112 + w] : 0.f;
            }
        } else {
#pragma unroll
            for (int i = 0; i < 2; ++i) {
                long off = (long)(k0 + b_r[i]) * p.ldb + n0 + b_c[i];
                float4 v = *(const float4*)(B1 + off);
                if (BLOAD == 1) {
                    float4 u = *(const float4*)(B2 + off);
                    v.x += u.x; v.y += u.y; v.z += u.z; v.w += u.w;
                } else if (BLOAD == 3) {
                    float4 u = *(const float4*)(B2 + off);
                    v.x = w0 * v.x + w1 * u.x; v.y = w0 * v.y + w1 * u.y;
                    v.z = w0 * v.z + w1 * u.z; v.w = w0 * v.w + w1 * u.w;
                }
                bR[i] = v;
            }
        }
    };
    auto storeTile = [&](int buf) {
        uint4 t0 = make_uint4(f2tf(aF[0]), f2tf(aF[1]), f2tf(aF[2]), f2tf(aF[3]));
        uint4 t1 = make_uint4(f2tf(aF[4]), f2tf(aF[5]), f2tf(aF[6]), f2tf(aF[7]));
        *(uint4*)&As[buf][a_r][a_k]     = t0;
        *(uint4*)&As[buf][a_r][a_k + 4] = t1;
        if (BLOAD == 2) {
#pragma unroll
            for (int i = 0; i < 8; ++i) Bs[buf][s_k[i]][s_n[i]] = f2tf(bS[i]);
        } else {
#pragma unroll
            for (int i = 0; i < 2; ++i) {
                uint4 t = make_uint4(f2tf(bR[i].x), f2tf(bR[i].y), f2tf(bR[i].z), f2tf(bR[i].w));
                *(uint4*)&Bs[buf][b_r[i]][b_c[i]] = t;
            }
        }
    };

    float acc[4][4][4];
#pragma unroll
    for (int a = 0; a < 4; ++a)
#pragma unroll
        for (int b = 0; b < 4; ++b)
#pragma unroll
            for (int c = 0; c < 4; ++c) acc[a][b][c] = 0.f;

    loadTile(0);
    storeTile(0);
    __syncthreads();
    int buf = 0;
    for (int k0 = 0; k0 < p.K; k0 += 16) {
        bool more = (k0 + 16 < p.K);
        if (more) loadTile(k0 + 16);     // global prefetch into regs
#pragma unroll
        for (int k8 = 0; k8 < 2; ++k8) {
            int kb = k8 * 8;
            unsigned af[4][4], bf[4][2];
#pragma unroll
            for (int mf = 0; mf < 4; ++mf) {
                int r = mw + mf * 16 + quad;
                af[mf][0] = As[buf][r][kb + tig];
                af[mf][1] = As[buf][r + 8][kb + tig];
                af[mf][2] = As[buf][r][kb + tig + 4];
                af[mf][3] = As[buf][r + 8][kb + tig + 4];
            }
#pragma unroll
            for (int nf = 0; nf < 4; ++nf) {
                int cb = nw + nf * 8 + quad;
                bf[nf][0] = Bs[buf][kb + tig][cb];
                bf[nf][1] = Bs[buf][kb + tig + 4][cb];
            }
#pragma unroll
            for (int mf = 0; mf < 4; ++mf)
#pragma unroll
                for (int nf = 0; nf < 4; ++nf)
                    mma_tf32(acc[mf][nf], af[mf], bf[nf]);
        }
        if (more) storeTile(buf ^ 1);    // fill other buffer (disjoint)
        __syncthreads();
        buf ^= 1;
    }

    // epilogue
#pragma unroll
    for (int mf = 0; mf < 4; ++mf) {
#pragma unroll
        for (int half = 0; half < 2; ++half) {
            int m = mw + mf * 16 + quad + half * 8;
            float sc = 0.f, bb = 0.f;
            if (EPI == 0 || EPI == 3) { sc = sv[m]; bb = bv[m]; }
            if (EPI == 2) { bb = bv[m]; }
#pragma unroll
            for (int nf = 0; nf < 4; ++nf) {
                int n = n0 + nw + nf * 8 + tig * 2;
                long o = (long)(m0 + m) * p.ldc + n;
                float vx = acc[mf][nf][half * 2 + 0];
                float vy = acc[mf][nf][half * 2 + 1];
                if (EPI == 0) {
                    vx = fmaxf(vx * sc + bb, 0.f);
                    vy = fmaxf(vy * sc + bb, 0.f);
                } else if (EPI == 1) {
                    float2 bn = *(const float2*)(bv + n);
                    vx += bn.x; vy += bn.y;
                } else if (EPI == 2) {
                    float2 r1 = *(const float2*)(R1 + o);
                    float2 r2 = *(const float2*)(R2 + o);
                    vx = sigm(vx + bb) * (r1.x + r2.x);
                    vy = sigm(vy + bb) * (r1.y + r2.y);
                } else {
                    float2 r1 = *(const float2*)(R1 + o);
                    vx = fmaxf(vx * sc + bb, 0.f) + r1.x;
                    vy = fmaxf(vy * sc + bb, 0.f) + r1.y;
                }
                *(float2*)(C + o) = make_float2(vx, vy);
            }
        }
    }
}

// ---------------------------------------------------------------------------
// Kernel 3: persistent GRU scan (R13 known-good scalar version)
// ---------------------------------------------------------------------------
__global__ __launch_bounds__(256) void scan_kernel(
    const float* __restrict__ whh_h, const float* __restrict__ bhh_h,
    const float* __restrict__ whh_w, const float* __restrict__ bhh_w,
    const float* __restrict__ gih, const float* __restrict__ giw,
    float* __restrict__ oh, float* __restrict__ ow)
{
    extern __shared__ float sm[];
    float* Ws = sm;              // 384*129
    float* Hs = sm + 384 * 129;  // 14*128

    int dir = blockIdx.x >> 6;
    int blk = blockIdx.x & 63;
    const float* W   = dir ? whh_w : whh_h;
    const float* bhh = dir ? bhh_w : bhh_h;
    const float* gi  = dir ? giw : gih;
    float* outp      = dir ? ow : oh;

    for (int i = threadIdx.x; i < 384 * 128; i += 256)
        Ws[(i >> 7) * 129 + (i & 127)] = W[i];
    for (int i = threadIdx.x; i < 14 * 128; i += 256) Hs[i] = 0.f;

    int c   = threadIdx.x & 127;
    int sub = threadIdx.x >> 7;
    float br = bhh[c], bz = bhh[128 + c], bn = bhh[256 + c];

    int gbase[7], hrow[7];
    long obase[7];
#pragma unroll
    for (int i = 0; i < 7; ++i) {
        int s = blk * 14 + sub * 7 + i;
        int b = s / 112, pos = s - b * 112;
        gbase[i] = s * 384 + c;
        hrow[i]  = (sub * 7 + i) * 128;
        long base = (long)(b * 128 + c) * 12544;
        obase[i] = dir ? (base + (long)pos * 112) : (base + pos);
    }
    int ostep = dir ? 1 : 112;
    const float* wr_p = Ws + c * 129;
    const float* wz_p = Ws + (128 + c) * 129;
    const float* wn_p = Ws + (256 + c) * 129;
    __syncthreads();

    for (int t = 0; t < 112; ++t) {
        const float* gip = gi + (long)t * 344064;
        float gr[7], gz[7], gn[7];
#pragma unroll
        for (int i = 0; i < 7; ++i) {
            gr[i] = gip[gbase[i]];
            gz[i] = gip[gbase[i] + 128];
            gn[i] = gip[gbase[i] + 256];
        }
        float aR[7], aZ[7], aN[7];
#pragma unroll
        for (int i = 0; i < 7; ++i) { aR[i] = br; aZ[i] = bz; aN[i] = bn; }

#pragma unroll 4
        for (int k = 0; k < 128; ++k) {
            float wr = wr_p[k], wz = wz_p[k], wn = wn_p[k];
#pragma unroll
            for (int i = 0; i < 7; ++i) {
                float h = Hs[hrow[i] + k];
                aR[i] = fmaf(wr, h, aR[i]);
                aZ[i] = fmaf(wz, h, aZ[i]);
                aN[i] = fmaf(wn, h, aN[i]);
            }
        }
        float hn[7];
#pragma unroll
        for (int i = 0; i < 7; ++i) {
            float hold = Hs[hrow[i] + c];
            float r = sigm(gr[i] + aR[i]);
            float z = sigm(gz[i] + aZ[i]);
            float n = tanh_f(gn[i] + r * aN[i]);
            hn[i] = (1.f - z) * n + z * hold;
        }
        __syncthreads();
#pragma unroll
        for (int i = 0; i < 7; ++i) {
            Hs[hrow[i] + c] = hn[i];
            outp[obase[i] + (long)t * ostep] = hn[i];
        }
        __syncthreads();
    }
}

// ---------------------------------------------------------------------------
// Router
// ---------------------------------------------------------------------------
__global__ void router_stats_kernel(const float* __restrict__ x2, float* __restrict__ ctx) {
    int b = blockIdx.x >> 7;
    int c = blockIdx.x & 127;
    const float* p = x2 + (long)(b * 128 + c) * HWP;
    float gs = 0.f, fs = 0.f;
    for (int i = threadIdx.x; i < HWP; i += 256) {
        int h = i / 112, w = i - h * 112;
        float v = p[i];
        gs += v;
        float lap = 4.f * v;
        if (h > 0)   lap -= p[i - 112];
        if (h < 111) lap -= p[i + 112];
        if (w > 0)   lap -= p[i - 1];
        if (w < 111) lap -= p[i + 1];
        fs += fabsf(lap);
    }
    __shared__ float sg[256], sf[256];
    sg[threadIdx.x] = gs; sf[threadIdx.x] = fs;
    __syncthreads();
    for (int st = 128; st > 0; st >>= 1) {
        if (threadIdx.x < st) {
            sg[threadIdx.x] += sg[threadIdx.x + st];
            sf[threadIdx.x] += sf[threadIdx.x + st];
        }
        __syncthreads();
    }
    if (threadIdx.x == 0) {
        ctx[b * 256 + c]       = sg[0] * (1.f / 12544.f);
        ctx[b * 256 + 128 + c] = sf[0] * (1.f / 12544.f);
    }
}

__global__ void router_fc_kernel(const float* __restrict__ ctx,
                                 const float* __restrict__ fcw,
                                 const float* __restrict__ fcb,
                                 float* __restrict__ wts) {
    int b = threadIdx.x >> 5;
    int lane = threadIdx.x & 31;
    float l0 = 0.f, l1 = 0.f;
    for (int j = lane; j < 256; j += 32) {
        float v = ctx[b * 256 + j];
        l0 += v * fcw[j];
        l1 += v * fcw[256 + j];
    }
#pragma unroll
    for (int off = 16; off; off >>= 1) {
        l0 += __shfl_down_sync(0xffffffffu, l0, off);
        l1 += __shfl_down_sync(0xffffffffu, l1, off);
    }
    if (lane == 0) {
        l0 += fcb[0]; l1 += fcb[1];
        float mx = fmaxf(l0, l1);
        float e0 = expf(l0 - mx), e1 = expf(l1 - mx);
        float inv = 1.f / (e0 + e1);
        wts[b * 2]     = e0 * inv;
        wts[b * 2 + 1] = e1 * inv;
    }
}

// ---------------------------------------------------------------------------
// Launch
// ---------------------------------------------------------------------------
extern "C" void kernel_launch(void* const* d_in, const int* in_sizes, int n_in,
                              void* d_out, int out_size) {
    const float* l        = (const float*)d_in[0];
    const float* m        = (const float*)d_in[1];
    const float* s        = (const float*)d_in[2];
    const float* p_in_w   = (const float*)d_in[3];
    const float* p_in_s   = (const float*)d_in[4];
    const float* p_in_b   = (const float*)d_in[5];
    const float* gh_wih   = (const float*)d_in[6];
    const float* gh_whh   = (const float*)d_in[7];
    const float* gh_bih   = (const float*)d_in[8];
    const float* gh_bhh   = (const float*)d_in[9];
    const float* gw_wih   = (const float*)d_in[10];
    const float* gw_whh   = (const float*)d_in[11];
    const float* gw_bih   = (const float*)d_in[12];
    const float* gw_bhh   = (const float*)d_in[13];
    const float* gate_w   = (const float*)d_in[14];
    const float* gate_b   = (const float*)d_in[15];
    const float* p_out_w  = (const float*)d_in[16];
    const float* p_out_s  = (const float*)d_in[17];
    const float* p_out_b  = (const float*)d_in[18];
    const float* exp_w    = (const float*)d_in[19];
    const float* exp_s    = (const float*)d_in[20];
    const float* exp_b    = (const float*)d_in[21];
    const float* fc_w     = (const float*)d_in[22];
    const float* fc_b     = (const float*)d_in[23];
    const float* fuse_w   = (const float*)d_in[24];
    const float* fuse_s   = (const float*)d_in[25];
    const float* fuse_b   = (const float*)d_in[26];

    float* pool = nullptr;
    cudaGetSymbolAddress((void**)&pool, g_pool);

    const int SCAN_SMEM = (384 * 129 + 14 * 128) * 4;
    cudaFuncSetAttribute(scan_kernel, cudaFuncAttributeMaxDynamicSharedMemorySize, SCAN_SMEM);

    const int NBLK = (NTOT + 255) / 256;
    const dim3 TC_GRID(98, 1, 8);    // n: 98*128 = 12544

    // 1. resize + concat, weight transposes
    resize_concat_kernel<<<NBLK, 256>>>(l, m, s, pool + OFF_CAT);
    transpose_wih_kernel<<<192, 256>>>(gh_wih, pool + OFF_WTH);
    transpose_wih_kernel<<<192, 256>>>(gw_wih, pool + OFF_WTW);

    // 2. p_in (tf32 TC)
    {
        GemmP P = {};
        P.A = p_in_w; P.lda = 384; P.K = 384;
        P.B1 = pool + OFF_CAT; P.ldb = HWP; P.bzB = 384L * HWP;
        P.C = pool + OFF_X; P.ldc = HWP; P.bzC = 128L * HWP;
        P.sv = p_in_s; P.bv = p_in_b;
        gemm_tc<0, 0, 0><<<TC_GRID, 256>>>(P);
    }

    // 3. gi GEMMs (tf32 TC, pack fused into A-gather)
    {
        GemmP P = {};
        P.A = pool + OFF_X; P.K = 128;
        P.B1 = pool + OFF_WTH; P.ldb = 384; P.bzB = 0;
        P.C = pool + OFF_GIH; P.ldc = 384; P.bzC = 0;
        P.bv = gh_bih;
        gemm_tc<1, 0, 1><<<dim3(3, 784, 1), 256>>>(P);
        P.B1 = pool + OFF_WTW;
        P.C = pool + OFF_GIW; P.bv = gw_bih;
        gemm_tc<2, 0, 1><<<dim3(3, 784, 1), 256>>>(P);
    }

    // 4. GRU scans (scalar, known-good)
    scan_kernel<<<128, 256, SCAN_SMEM>>>(gh_whh, gh_bhh, gw_whh, gw_bhh,
                                         pool + OFF_GIH, pool + OFF_GIW,
                                         pool + OFF_OH, pool + OFF_OW);

    // 5. gate (tf32 TC)
    {
        GemmP P = {};
        P.A = gate_w; P.lda = 128; P.K = 128;
        P.B1 = pool + OFF_OH; P.B2 = pool + OFF_OW; P.ldb = HWP; P.bzB = 128L * HWP;
        P.C = pool + OFF_T2; P.ldc = HWP; P.bzC = 128L * HWP;
        P.bv = gate_b;
        P.R1 = pool + OFF_OH; P.R2 = pool + OFF_OW; P.bzR = 128L * HWP;
        gemm_tc<0, 1, 2><<<TC_GRID, 256>>>(P);
    }

    // 6. p_out (tf32 TC)
    {
        GemmP P = {};
        P.A = p_out_w; P.lda = 128; P.K = 128;
        P.B1 = pool + OFF_T2; P.ldb = HWP; P.bzB = 128L * HWP;
        P.C = pool + OFF_X2; P.ldc = HWP; P.bzC = 128L * HWP;
        P.sv = p_out_s; P.bv = p_out_b;
        P.R1 = pool + OFF_X; P.bzR = 128L * HWP;
        gemm_tc<0, 0, 3><<<TC_GRID, 256>>>(P);
    }

    // 7. router
    router_stats_kernel<<<1024, 256>>>(pool + OFF_X2, pool + OFF_CTX);
    router_fc_kernel<<<1, 256>>>(pool + OFF_CTX, fc_w, fc_b, pool + OFF_WTS);

    // 8. experts (tf32 TC, both experts in ONE launch: z = (e<<3)|batch)
    {
        GemmP P = {};
        P.A = exp_w; P.lda = 1152; P.K = 1152;
        P.B1 = pool + OFF_X2; P.bzB = 128L * HWP;
        P.C = pool + OFF_MOE; P.ldc = HWP; P.bzC = 128L * HWP;
        P.sv = exp_s; P.bv = exp_b;
        gemm_tc<0, 2, 0><<<dim3(98, 1, 16), 256>>>(P);
    }

    // 9. fuse (tf32 TC)
    {
        GemmP P = {};
        P.A = fuse_w; P.lda = 128; P.K = 128;
        P.B1 = pool + OFF_MOE; P.B2 = pool + OFF_MOE + NTOT;
        P.ldb = HWP; P.bzB = 128L * HWP;
        P.wts = pool + OFF_WTS;
        P.C = (float*)d_out; P.ldc = HWP; P.bzC = 128L * HWP;
        P.sv = fuse_s; P.bv = fuse_b;
        gemm_tc<0, 3, 0><<<TC_GRID, 256>>>(P);
    }
}